// round 1
// baseline (speedup 1.0000x reference)
#include <cuda_runtime.h>
#include <math.h>

#define TPB 256

// Fused per-image pipeline. One CTA = one image.
// Layout constants:
//  x:        [28][28]           (784)
//  pooled1:  [8][11][11]        (968)   -> stored in s_buf
//  pooled2:  [10][3][3] = f     (90)
//  h:        [32], k: [40]
//  pooled3:  [10][13][13]       (1690)  -> stored in s_buf (reuse)
//  pooled4:  [20][4][4]         (320)
//  y1:       [50], logits: [10]
__global__ __launch_bounds__(TPB) void fused_net_kernel(
    const float* __restrict__ x,
    const float* __restrict__ kf_w1, const float* __restrict__ kf_b1,
    const float* __restrict__ kf_w2, const float* __restrict__ kf_b2,
    const float* __restrict__ kf_fc1_w, const float* __restrict__ kf_fc1_b,
    const float* __restrict__ kf_fc2_w, const float* __restrict__ kf_fc2_b,
    const float* __restrict__ conv2_w, const float* __restrict__ conv2_b,
    const float* __restrict__ fc1_w, const float* __restrict__ fc1_b,
    const float* __restrict__ fc2_w, const float* __restrict__ fc2_b,
    float* __restrict__ out)
{
    __shared__ float s_x[784];
    __shared__ float s_buf[1690];   // pooled1 then pooled3
    __shared__ float s_f[90];
    __shared__ float s_h[32];
    __shared__ float s_k[40];
    __shared__ float s_p4[320];
    __shared__ float s_y1[64];
    __shared__ float s_logits[16];
    __shared__ float s_w1[392];
    __shared__ float s_b1[8];
    __shared__ float s_w2[2000];
    __shared__ float s_b2[10];
    __shared__ float s_cw[5000];
    __shared__ float s_cb[20];

    const int n   = blockIdx.x;
    const int tid = threadIdx.x;

    // ---- Stage 0: load image + conv weights into smem ----
    const float* xn = x + n * 784;
    for (int i = tid; i < 784;  i += TPB) s_x[i]  = xn[i];
    for (int i = tid; i < 392;  i += TPB) s_w1[i] = kf_w1[i];
    for (int i = tid; i < 2000; i += TPB) s_w2[i] = kf_w2[i];
    for (int i = tid; i < 5000; i += TPB) s_cw[i] = conv2_w[i];
    if (tid < 8)                  s_b1[tid]      = kf_b1[tid];
    if (tid >= 32 && tid < 42)    s_b2[tid - 32] = kf_b2[tid - 32];
    if (tid >= 64 && tid < 84)    s_cb[tid - 64] = conv2_b[tid - 64];
    __syncthreads();

    // ---- Stage 1: conv7x7 (1->8) + maxpool2 + relu -> pooled1 [8][11][11] ----
    for (int it = tid; it < 968; it += TPB) {
        const int c   = it / 121;
        const int rem = it - c * 121;
        const int pi  = rem / 11;
        const int pj  = rem - pi * 11;
        float w[49];
        #pragma unroll
        for (int q = 0; q < 49; q++) w[q] = s_w1[c * 49 + q];
        const float b = s_b1[c];
        float a00 = b, a01 = b, a10 = b, a11 = b;
        #pragma unroll
        for (int ar = 0; ar < 8; ar++) {
            float a[8];
            const float* row = &s_x[(2 * pi + ar) * 28 + 2 * pj];
            #pragma unroll
            for (int v = 0; v < 8; v++) a[v] = row[v];
            if (ar < 7) {
                #pragma unroll
                for (int v = 0; v < 7; v++) {
                    const float wt = w[ar * 7 + v];
                    a00 = fmaf(a[v],     wt, a00);
                    a01 = fmaf(a[v + 1], wt, a01);
                }
            }
            if (ar >= 1) {
                #pragma unroll
                for (int v = 0; v < 7; v++) {
                    const float wb = w[(ar - 1) * 7 + v];
                    a10 = fmaf(a[v],     wb, a10);
                    a11 = fmaf(a[v + 1], wb, a11);
                }
            }
        }
        const float m = fmaxf(fmaxf(a00, a01), fmaxf(a10, a11));
        s_buf[it] = fmaxf(m, 0.0f);
    }
    __syncthreads();

    // ---- Stage 2: conv5x5 (8->10) + maxpool2 + relu -> f [10][3][3] ----
    for (int it = tid; it < 90; it += TPB) {
        const int c   = it / 9;
        const int rem = it - c * 9;
        const int pi  = rem / 3;
        const int pj  = rem - pi * 3;
        const float b = s_b2[c];
        float a00 = b, a01 = b, a10 = b, a11 = b;
        for (int ci = 0; ci < 8; ci++) {
            float w[25];
            #pragma unroll
            for (int q = 0; q < 25; q++) w[q] = s_w2[(c * 8 + ci) * 25 + q];
            #pragma unroll
            for (int ar = 0; ar < 6; ar++) {
                float a[6];
                const float* row = &s_buf[ci * 121 + (2 * pi + ar) * 11 + 2 * pj];
                #pragma unroll
                for (int v = 0; v < 6; v++) a[v] = row[v];
                if (ar < 5) {
                    #pragma unroll
                    for (int v = 0; v < 5; v++) {
                        const float wt = w[ar * 5 + v];
                        a00 = fmaf(a[v],     wt, a00);
                        a01 = fmaf(a[v + 1], wt, a01);
                    }
                }
                if (ar >= 1) {
                    #pragma unroll
                    for (int v = 0; v < 5; v++) {
                        const float wb = w[(ar - 1) * 5 + v];
                        a10 = fmaf(a[v],     wb, a10);
                        a11 = fmaf(a[v + 1], wb, a11);
                    }
                }
            }
        }
        const float m = fmaxf(fmaxf(a00, a01), fmaxf(a10, a11));
        s_f[it] = fmaxf(m, 0.0f);
    }
    __syncthreads();

    // ---- Stage 3: hypernetwork FCs: 90 -> 32 (relu) -> 40 kernel coeffs ----
    if (tid < 32) {
        float acc = kf_fc1_b[tid];
        #pragma unroll 9
        for (int q = 0; q < 90; q++)
            acc = fmaf(s_f[q], kf_fc1_w[tid * 90 + q], acc);
        s_h[tid] = fmaxf(acc, 0.0f);
    }
    __syncthreads();
    if (tid < 40) {
        float acc = kf_fc2_b[tid];
        #pragma unroll
        for (int q = 0; q < 32; q++)
            acc = fmaf(s_h[q], kf_fc2_w[tid * 32 + q], acc);
        s_k[tid] = acc;
    }
    __syncthreads();

    // ---- Stage 4: per-sample dynamic 2x2 conv + maxpool2 + relu -> pooled3 [10][13][13] ----
    for (int it = tid; it < 1690; it += TPB) {
        const int c   = it / 169;
        const int rem = it - c * 169;
        const int pi  = rem / 13;
        const int pj  = rem - pi * 13;
        const float k00 = s_k[c * 4 + 0];
        const float k01 = s_k[c * 4 + 1];
        const float k10 = s_k[c * 4 + 2];
        const float k11 = s_k[c * 4 + 3];
        float a[3][3];
        #pragma unroll
        for (int u = 0; u < 3; u++)
            #pragma unroll
            for (int v = 0; v < 3; v++)
                a[u][v] = s_x[(2 * pi + u) * 28 + 2 * pj + v];
        float m = -INFINITY;
        #pragma unroll
        for (int di = 0; di < 2; di++)
            #pragma unroll
            for (int dj = 0; dj < 2; dj++) {
                float cv = a[di][dj] * k00;
                cv = fmaf(a[di][dj + 1],     k01, cv);
                cv = fmaf(a[di + 1][dj],     k10, cv);
                cv = fmaf(a[di + 1][dj + 1], k11, cv);
                m = fmaxf(m, cv);
            }
        s_buf[it] = fmaxf(m, 0.0f);
    }
    __syncthreads();

    // ---- Stage 5: conv5x5 (10->20) + maxpool2 + relu -> pooled4 [20][4][4] ----
    for (int it = tid; it < 320; it += TPB) {
        const int c   = it / 16;
        const int rem = it - c * 16;
        const int pi  = rem / 4;
        const int pj  = rem - pi * 4;
        const float b = s_cb[c];
        float a00 = b, a01 = b, a10 = b, a11 = b;
        for (int ci = 0; ci < 10; ci++) {
            float w[25];
            #pragma unroll
            for (int q = 0; q < 25; q++) w[q] = s_cw[(c * 10 + ci) * 25 + q];
            #pragma unroll
            for (int ar = 0; ar < 6; ar++) {
                float a[6];
                const float* row = &s_buf[ci * 169 + (2 * pi + ar) * 13 + 2 * pj];
                #pragma unroll
                for (int v = 0; v < 6; v++) a[v] = row[v];
                if (ar < 5) {
                    #pragma unroll
                    for (int v = 0; v < 5; v++) {
                        const float wt = w[ar * 5 + v];
                        a00 = fmaf(a[v],     wt, a00);
                        a01 = fmaf(a[v + 1], wt, a01);
                    }
                }
                if (ar >= 1) {
                    #pragma unroll
                    for (int v = 0; v < 5; v++) {
                        const float wb = w[(ar - 1) * 5 + v];
                        a10 = fmaf(a[v],     wb, a10);
                        a11 = fmaf(a[v + 1], wb, a11);
                    }
                }
            }
        }
        const float m = fmaxf(fmaxf(a00, a01), fmaxf(a10, a11));
        s_p4[it] = fmaxf(m, 0.0f);
    }
    __syncthreads();

    // ---- Stage 6: fc1 320->50 (relu), warp-per-output ----
    const int warp = tid >> 5;
    const int lane = tid & 31;
    for (int o = warp; o < 50; o += 8) {
        float acc = 0.0f;
        const float* wrow = fc1_w + o * 320;
        #pragma unroll
        for (int q = 0; q < 10; q++)
            acc = fmaf(s_p4[lane + 32 * q], wrow[lane + 32 * q], acc);
        #pragma unroll
        for (int off = 16; off > 0; off >>= 1)
            acc += __shfl_xor_sync(0xffffffffu, acc, off);
        if (lane == 0) s_y1[o] = fmaxf(acc + fc1_b[o], 0.0f);
    }
    __syncthreads();

    // ---- Stage 7: fc2 50->10 + log_softmax ----
    if (tid < 10) {
        float acc = fc2_b[tid];
        #pragma unroll 10
        for (int q = 0; q < 50; q++)
            acc = fmaf(s_y1[q], fc2_w[tid * 50 + q], acc);
        s_logits[tid] = acc;
    }
    __syncthreads();
    if (tid == 0) {
        float mx = s_logits[0];
        #pragma unroll
        for (int q = 1; q < 10; q++) mx = fmaxf(mx, s_logits[q]);
        float s = 0.0f;
        #pragma unroll
        for (int q = 0; q < 10; q++) s += expf(s_logits[q] - mx);
        s_logits[12] = mx + logf(s);   // lse
    }
    __syncthreads();
    if (tid < 10) out[n * 10 + tid] = s_logits[tid] - s_logits[12];
}

extern "C" void kernel_launch(void* const* d_in, const int* in_sizes, int n_in,
                              void* d_out, int out_size) {
    const float* x        = (const float*)d_in[0];
    const float* kf_w1    = (const float*)d_in[1];
    const float* kf_b1    = (const float*)d_in[2];
    const float* kf_w2    = (const float*)d_in[3];
    const float* kf_b2    = (const float*)d_in[4];
    const float* kf_fc1_w = (const float*)d_in[5];
    const float* kf_fc1_b = (const float*)d_in[6];
    const float* kf_fc2_w = (const float*)d_in[7];
    const float* kf_fc2_b = (const float*)d_in[8];
    const float* conv2_w  = (const float*)d_in[9];
    const float* conv2_b  = (const float*)d_in[10];
    const float* fc1_w    = (const float*)d_in[11];
    const float* fc1_b    = (const float*)d_in[12];
    const float* fc2_w    = (const float*)d_in[13];
    const float* fc2_b    = (const float*)d_in[14];
    float* out = (float*)d_out;

    const int n = in_sizes[0] / 784;
    fused_net_kernel<<<n, TPB>>>(x, kf_w1, kf_b1, kf_w2, kf_b2,
                                 kf_fc1_w, kf_fc1_b, kf_fc2_w, kf_fc2_b,
                                 conv2_w, conv2_b, fc1_w, fc1_b, fc2_w, fc2_b,
                                 out);
}

// round 2
// speedup vs baseline: 1.2006x; 1.2006x over previous
#include <cuda_runtime.h>
#include <math.h>

#define TPB 256
typedef unsigned long long u64;

// ---- packed fp32x2 helpers (sm_103a) ----
__device__ __forceinline__ u64 packdup(float a) {
    u64 r; asm("mov.b64 %0,{%1,%1};" : "=l"(r) : "f"(a)); return r;
}
__device__ __forceinline__ u64 fma2(u64 a, u64 b, u64 c) {
    u64 d; asm("fma.rn.f32x2 %0,%1,%2,%3;" : "=l"(d) : "l"(a), "l"(b), "l"(c)); return d;
}
__device__ __forceinline__ void unpk(u64 x, float& lo, float& hi) {
    asm("mov.b64 {%0,%1},%2;" : "=f"(lo), "=f"(hi) : "l"(x));
}

// ---- shared memory layout (floats) ----
#define OFF_W1P 0        // [4 pair][49] x2      (392)
#define OFF_W2P 392      // [5 pair][8ci][25] x2 (2000)
#define OFF_CWP 2392     // [10 pair][10ci][25]x2(5000)
#define OFF_B1P 7392     // (8)
#define OFF_B2P 7400     // (10)
#define OFF_CBP 7410     // (20)
#define OFF_X   7432     // [28][28]             (784)   16B aligned
#define OFF_BUF 8216     // pooled1 [8][11][11] then pooled3 [10][13][13] (1690)
#define OFF_F   9906     // (90)
#define OFF_H   9996     // (32)
#define OFF_K   10028    // (40)
#define OFF_P4  10068    // [20][4][4]           (320)   16B aligned
#define OFF_Y1  10388    // (64)
#define OFF_LG  10452    // (16)
#define OFF_K1T 10468    // kf_fc1_w^T [90][33]  (2970)
#define OFF_K2T 13438    // kf_fc2_w^T [32][41]  (1312)
#define OFF_F2T 14750    // fc2_w^T    [50][11]  (550)
#define SMEM_FLOATS 15300
#define SMEM_BYTES  (SMEM_FLOATS * 4)

__global__ __launch_bounds__(TPB, 3) void fused_net_kernel(
    const float* __restrict__ x,
    const float* __restrict__ kf_w1, const float* __restrict__ kf_b1,
    const float* __restrict__ kf_w2, const float* __restrict__ kf_b2,
    const float* __restrict__ kf_fc1_w, const float* __restrict__ kf_fc1_b,
    const float* __restrict__ kf_fc2_w, const float* __restrict__ kf_fc2_b,
    const float* __restrict__ conv2_w, const float* __restrict__ conv2_b,
    const float* __restrict__ fc1_w, const float* __restrict__ fc1_b,
    const float* __restrict__ fc2_w, const float* __restrict__ fc2_b,
    float* __restrict__ out)
{
    extern __shared__ __align__(16) float s[];

    const int n   = blockIdx.x;
    const int tid = threadIdx.x;

    // ================= Stage 0: stage inputs into smem =================
    {
        const float4* x4 = (const float4*)(x + n * 784);
        float4* sx4 = (float4*)(s + OFF_X);
        for (int i = tid; i < 196; i += TPB) sx4[i] = x4[i];

        // conv weights interleaved by channel pair: pair p holds (c=2p, c=2p+1)
        for (int i = tid; i < 392; i += TPB) {
            int c = i / 49, q = i - c * 49;
            s[OFF_W1P + (((c >> 1) * 49 + q) << 1) + (c & 1)] = kf_w1[i];
        }
        for (int i = tid; i < 2000; i += TPB) {
            int c = i / 200, r = i - c * 200;
            s[OFF_W2P + (((c >> 1) * 200 + r) << 1) + (c & 1)] = kf_w2[i];
        }
        for (int i = tid; i < 5000; i += TPB) {
            int c = i / 250, r = i - c * 250;
            s[OFF_CWP + (((c >> 1) * 250 + r) << 1) + (c & 1)] = conv2_w[i];
        }
        if (tid < 8)  s[OFF_B1P + tid] = kf_b1[tid];
        if (tid < 10) s[OFF_B2P + tid] = kf_b2[tid];
        if (tid < 20) s[OFF_CBP + tid] = conv2_b[tid];

        // FC weight transposes (padded strides -> conflict-free reads)
        for (int i = tid; i < 2880; i += TPB) {
            int o = i / 90, q = i - o * 90;
            s[OFF_K1T + q * 33 + o] = kf_fc1_w[i];     // [32][90] -> [90][33]
        }
        for (int i = tid; i < 1280; i += TPB) {
            int o = i >> 5, q = i & 31;
            s[OFF_K2T + q * 41 + o] = kf_fc2_w[i];     // [40][32] -> [32][41]
        }
        for (int i = tid; i < 500; i += TPB) {
            int o = i / 50, q = i - o * 50;
            s[OFF_F2T + q * 11 + o] = fc2_w[i];        // [10][50] -> [50][11]
        }
    }
    __syncthreads();

    // ===== Stage 1: conv7x7 (1->8) + maxpool2 + relu -> pooled1 [8][11][11] =====
    // thread = (channel-pair cp, pooled row pi, col quarter q). 176 threads.
    if (tid < 176) {
        const int cp = tid / 44;
        const int t  = tid - cp * 44;
        const int pi = t >> 2;
        const int q  = t & 3;
        const int c0 = 6 * q;                   // first input col
        const u64* wp = (const u64*)(s + OFF_W1P) + cp * 49;
        const u64 bias = ((const u64*)(s + OFF_B1P))[cp];
        u64 acc[2][6];
        #pragma unroll
        for (int cr = 0; cr < 2; cr++)
            #pragma unroll
            for (int j = 0; j < 6; j++) acc[cr][j] = bias;

        for (int r = 0; r < 8; r++) {
            const float* row = s + OFF_X + (2 * pi + r) * 28;
            u64 ap[12];
            #pragma unroll
            for (int j = 0; j < 12; j++) {
                float av = (c0 + j < 28) ? row[c0 + j] : 0.0f;
                ap[j] = packdup(av);
            }
            if (r < 7) {
                const u64* w = wp + r * 7;
                #pragma unroll
                for (int v = 0; v < 7; v++) {
                    const u64 wv = w[v];
                    #pragma unroll
                    for (int j = 0; j < 6; j++) acc[0][j] = fma2(ap[j + v], wv, acc[0][j]);
                }
            }
            if (r >= 1) {
                const u64* w = wp + (r - 1) * 7;
                #pragma unroll
                for (int v = 0; v < 7; v++) {
                    const u64 wv = w[v];
                    #pragma unroll
                    for (int j = 0; j < 6; j++) acc[1][j] = fma2(ap[j + v], wv, acc[1][j]);
                }
            }
        }
        #pragma unroll
        for (int pl = 0; pl < 3; pl++) {
            const int pj = 3 * q + pl;
            if (pj < 11) {
                float a0, a1, b0, b1, e0, e1, d0, d1;
                unpk(acc[0][2 * pl],     a0, a1);
                unpk(acc[0][2 * pl + 1], b0, b1);
                unpk(acc[1][2 * pl],     e0, e1);
                unpk(acc[1][2 * pl + 1], d0, d1);
                float m0 = fmaxf(fmaxf(a0, b0), fmaxf(e0, d0));
                float m1 = fmaxf(fmaxf(a1, b1), fmaxf(e1, d1));
                s[OFF_BUF + (2 * cp)     * 121 + pi * 11 + pj] = fmaxf(m0, 0.0f);
                s[OFF_BUF + (2 * cp + 1) * 121 + pi * 11 + pj] = fmaxf(m1, 0.0f);
            }
        }
    }
    __syncthreads();

    // ===== Stage 2: conv5x5 (8->10) + maxpool2 + relu -> f [10][3][3] =====
    // thread = (cp, pi). 15 threads.
    if (tid < 15) {
        const int cp = tid / 3;
        const int pi = tid - cp * 3;
        const u64 bias = ((const u64*)(s + OFF_B2P))[cp];
        u64 acc[2][6];
        #pragma unroll
        for (int cr = 0; cr < 2; cr++)
            #pragma unroll
            for (int j = 0; j < 6; j++) acc[cr][j] = bias;

        for (int ci = 0; ci < 8; ci++) {
            const u64* wp = (const u64*)(s + OFF_W2P) + (cp * 8 + ci) * 25;
            const float* plane = s + OFF_BUF + ci * 121;
            for (int r = 0; r < 6; r++) {
                const float* row = plane + (2 * pi + r) * 11;
                u64 ap[11];
                #pragma unroll
                for (int j = 0; j < 11; j++) ap[j] = packdup(row[j]);
                if (r < 5) {
                    const u64* w = wp + r * 5;
                    #pragma unroll
                    for (int v = 0; v < 5; v++) {
                        const u64 wv = w[v];
                        #pragma unroll
                        for (int j = 0; j < 6; j++) acc[0][j] = fma2(ap[j + v], wv, acc[0][j]);
                    }
                }
                if (r >= 1) {
                    const u64* w = wp + (r - 1) * 5;
                    #pragma unroll
                    for (int v = 0; v < 5; v++) {
                        const u64 wv = w[v];
                        #pragma unroll
                        for (int j = 0; j < 6; j++) acc[1][j] = fma2(ap[j + v], wv, acc[1][j]);
                    }
                }
            }
        }
        #pragma unroll
        for (int pl = 0; pl < 3; pl++) {
            float a0, a1, b0, b1, e0, e1, d0, d1;
            unpk(acc[0][2 * pl],     a0, a1);
            unpk(acc[0][2 * pl + 1], b0, b1);
            unpk(acc[1][2 * pl],     e0, e1);
            unpk(acc[1][2 * pl + 1], d0, d1);
            float m0 = fmaxf(fmaxf(a0, b0), fmaxf(e0, d0));
            float m1 = fmaxf(fmaxf(a1, b1), fmaxf(e1, d1));
            s[OFF_F + (2 * cp)     * 9 + pi * 3 + pl] = fmaxf(m0, 0.0f);
            s[OFF_F + (2 * cp + 1) * 9 + pi * 3 + pl] = fmaxf(m1, 0.0f);
        }
    }
    __syncthreads();

    // ===== Stage 3: hypernet FCs 90->32 (relu) -> 40 =====
    if (tid < 32) {
        float acc = kf_fc1_b[tid];
        #pragma unroll 6
        for (int q = 0; q < 90; q++)
            acc = fmaf(s[OFF_F + q], s[OFF_K1T + q * 33 + tid], acc);
        s[OFF_H + tid] = fmaxf(acc, 0.0f);
    }
    __syncthreads();
    if (tid < 40) {
        float acc = kf_fc2_b[tid];
        #pragma unroll
        for (int q = 0; q < 32; q++)
            acc = fmaf(s[OFF_H + q], s[OFF_K2T + q * 41 + tid], acc);
        s[OFF_K + tid] = acc;
    }
    __syncthreads();

    // ===== Stage 4: dynamic 2x2 conv + maxpool2 + relu -> pooled3 [10][13][13] =====
    for (int it = tid; it < 1690; it += TPB) {
        const int c   = it / 169;
        const int rem = it - c * 169;
        const int pi  = rem / 13;
        const int pj  = rem - pi * 13;
        const float k00 = s[OFF_K + c * 4 + 0];
        const float k01 = s[OFF_K + c * 4 + 1];
        const float k10 = s[OFF_K + c * 4 + 2];
        const float k11 = s[OFF_K + c * 4 + 3];
        float a[3][3];
        #pragma unroll
        for (int u = 0; u < 3; u++)
            #pragma unroll
            for (int v = 0; v < 3; v++)
                a[u][v] = s[OFF_X + (2 * pi + u) * 28 + 2 * pj + v];
        float m = -INFINITY;
        #pragma unroll
        for (int di = 0; di < 2; di++)
            #pragma unroll
            for (int dj = 0; dj < 2; dj++) {
                float cv = a[di][dj] * k00;
                cv = fmaf(a[di][dj + 1],     k01, cv);
                cv = fmaf(a[di + 1][dj],     k10, cv);
                cv = fmaf(a[di + 1][dj + 1], k11, cv);
                m = fmaxf(m, cv);
            }
        s[OFF_BUF + it] = fmaxf(m, 0.0f);
    }
    __syncthreads();

    // ===== Stage 5: conv5x5 (10->20) + maxpool2 + relu -> pooled4 [20][4][4] =====
    // thread = (cp, pi, col half h). 80 threads.
    if (tid < 80) {
        const int cp = tid >> 3;
        const int t  = tid & 7;
        const int pi = t >> 1;
        const int h  = t & 1;
        const int c0 = 4 * h;
        const u64 bias = ((const u64*)(s + OFF_CBP))[cp];
        u64 acc[2][4];
        #pragma unroll
        for (int cr = 0; cr < 2; cr++)
            #pragma unroll
            for (int j = 0; j < 4; j++) acc[cr][j] = bias;

        for (int ci = 0; ci < 10; ci++) {
            const u64* wp = (const u64*)(s + OFF_CWP) + (cp * 10 + ci) * 25;
            const float* plane = s + OFF_BUF + ci * 169;
            for (int r = 0; r < 6; r++) {
                const float* row = plane + (2 * pi + r) * 13 + c0;
                u64 ap[8];
                #pragma unroll
                for (int j = 0; j < 8; j++) ap[j] = packdup(row[j]);
                if (r < 5) {
                    const u64* w = wp + r * 5;
                    #pragma unroll
                    for (int v = 0; v < 5; v++) {
                        const u64 wv = w[v];
                        #pragma unroll
                        for (int j = 0; j < 4; j++) acc[0][j] = fma2(ap[j + v], wv, acc[0][j]);
                    }
                }
                if (r >= 1) {
                    const u64* w = wp + (r - 1) * 5;
                    #pragma unroll
                    for (int v = 0; v < 5; v++) {
                        const u64 wv = w[v];
                        #pragma unroll
                        for (int j = 0; j < 4; j++) acc[1][j] = fma2(ap[j + v], wv, acc[1][j]);
                    }
                }
            }
        }
        #pragma unroll
        for (int pl = 0; pl < 2; pl++) {
            const int pj = 2 * h + pl;
            float a0, a1, b0, b1, e0, e1, d0, d1;
            unpk(acc[0][2 * pl],     a0, a1);
            unpk(acc[0][2 * pl + 1], b0, b1);
            unpk(acc[1][2 * pl],     e0, e1);
            unpk(acc[1][2 * pl + 1], d0, d1);
            float m0 = fmaxf(fmaxf(a0, b0), fmaxf(e0, d0));
            float m1 = fmaxf(fmaxf(a1, b1), fmaxf(e1, d1));
            s[OFF_P4 + (2 * cp)     * 16 + pi * 4 + pj] = fmaxf(m0, 0.0f);
            s[OFF_P4 + (2 * cp + 1) * 16 + pi * 4 + pj] = fmaxf(m1, 0.0f);
        }
    }
    __syncthreads();

    // ===== Stage 6: fc1 320->50 (relu), warp-per-output, float4 =====
    {
        const int warp = tid >> 5;
        const int lane = tid & 31;
        for (int o = warp; o < 50; o += 8) {
            const float4* wr = (const float4*)(fc1_w + o * 320);
            const float4* pr = (const float4*)(s + OFF_P4);
            float acc = 0.0f;
            #pragma unroll
            for (int k = 0; k < 3; k++) {
                const int i = lane + 32 * k;
                if (i < 80) {
                    float4 w4 = wr[i];
                    float4 p4 = pr[i];
                    acc = fmaf(w4.x, p4.x, fmaf(w4.y, p4.y,
                          fmaf(w4.z, p4.z, fmaf(w4.w, p4.w, acc))));
                }
            }
            #pragma unroll
            for (int off = 16; off > 0; off >>= 1)
                acc += __shfl_xor_sync(0xffffffffu, acc, off);
            if (lane == 0) s[OFF_Y1 + o] = fmaxf(acc + fc1_b[o], 0.0f);
        }
    }
    __syncthreads();

    // ===== Stage 7: fc2 50->10 + log_softmax =====
    if (tid < 10) {
        float acc = fc2_b[tid];
        #pragma unroll 10
        for (int q = 0; q < 50; q++)
            acc = fmaf(s[OFF_Y1 + q], s[OFF_F2T + q * 11 + tid], acc);
        s[OFF_LG + tid] = acc;
    }
    __syncthreads();
    if (tid == 0) {
        float mx = s[OFF_LG + 0];
        #pragma unroll
        for (int q = 1; q < 10; q++) mx = fmaxf(mx, s[OFF_LG + q]);
        float sum = 0.0f;
        #pragma unroll
        for (int q = 0; q < 10; q++) sum += expf(s[OFF_LG + q] - mx);
        s[OFF_LG + 12] = mx + logf(sum);
    }
    __syncthreads();
    if (tid < 10) out[n * 10 + tid] = s[OFF_LG + tid] - s[OFF_LG + 12];
}

extern "C" void kernel_launch(void* const* d_in, const int* in_sizes, int n_in,
                              void* d_out, int out_size) {
    const float* x        = (const float*)d_in[0];
    const float* kf_w1    = (const float*)d_in[1];
    const float* kf_b1    = (const float*)d_in[2];
    const float* kf_w2    = (const float*)d_in[3];
    const float* kf_b2    = (const float*)d_in[4];
    const float* kf_fc1_w = (const float*)d_in[5];
    const float* kf_fc1_b = (const float*)d_in[6];
    const float* kf_fc2_w = (const float*)d_in[7];
    const float* kf_fc2_b = (const float*)d_in[8];
    const float* conv2_w  = (const float*)d_in[9];
    const float* conv2_b  = (const float*)d_in[10];
    const float* fc1_w    = (const float*)d_in[11];
    const float* fc1_b    = (const float*)d_in[12];
    const float* fc2_w    = (const float*)d_in[13];
    const float* fc2_b    = (const float*)d_in[14];
    float* out = (float*)d_out;

    const int n = in_sizes[0] / 784;
    cudaFuncSetAttribute(fused_net_kernel,
                         cudaFuncAttributeMaxDynamicSharedMemorySize, SMEM_BYTES);
    fused_net_kernel<<<n, TPB, SMEM_BYTES>>>(x, kf_w1, kf_b1, kf_w2, kf_b2,
                                             kf_fc1_w, kf_fc1_b, kf_fc2_w, kf_fc2_b,
                                             conv2_w, conv2_b, fc1_w, fc1_b,
                                             fc2_w, fc2_b, out);
}

// round 3
// speedup vs baseline: 1.6262x; 1.3545x over previous
#include <cuda_runtime.h>
#include <math.h>

#define TPB 352
typedef unsigned long long u64;

// ---- packed fp32x2 helpers (sm_103a) ----
__device__ __forceinline__ u64 packdup(float a) {
    u64 r; asm("mov.b64 %0,{%1,%1};" : "=l"(r) : "f"(a)); return r;
}
__device__ __forceinline__ u64 fma2(u64 a, u64 b, u64 c) {
    u64 d; asm("fma.rn.f32x2 %0,%1,%2,%3;" : "=l"(d) : "l"(a), "l"(b), "l"(c)); return d;
}
__device__ __forceinline__ void unpk(u64 x, float& lo, float& hi) {
    asm("mov.b64 {%0,%1},%2;" : "=f"(lo), "=f"(hi) : "l"(x));
}

// ---- shared memory layout (floats) ----
// shared weights
#define OFF_W1P 0        // [4 pair][49] x2      (392)
#define OFF_W2P 392      // [5 pair][8ci][25] x2 (2000)
#define OFF_CWP 2392     // [10 pair][10ci][25]x2(5000)
#define OFF_B1P 7392     // (8)
#define OFF_B2P 7400     // (10)
#define OFF_CBP 7410     // (20) -> 7430 pad 7432
#define OFF_K1T 7432     // kf_fc1_w^T [90][33]  (2970) -> 10402
#define OFF_K2T 10402    // kf_fc2_w^T [32][41]  (1312) -> 11714
#define OFF_F2T 11714    // fc2_w^T    [50][11]  (550)  -> 12264 pad 12272
// per-image blocks (x2)
#define SH_IMG0 12272
#define IMG_STRIDE 3040
#define PX   0           // [28][28]   (784)
#define PBUF 784         // pooled1 [8][11][11] / pooled3 [10][13][13] (1690)
#define PF   2474        // (90)
#define PH   2564        // (32)
#define PK   2596        // (40)
#define PP4  2636        // [20][4][4] (320)
#define PY1  2956        // (64)
#define PLG  3020        // (16)
#define SMEM_FLOATS (SH_IMG0 + 2 * IMG_STRIDE)
#define SMEM_BYTES  (SMEM_FLOATS * 4)

__global__ __launch_bounds__(TPB, 3) void fused_net_kernel(
    const float* __restrict__ x,
    const float* __restrict__ kf_w1, const float* __restrict__ kf_b1,
    const float* __restrict__ kf_w2, const float* __restrict__ kf_b2,
    const float* __restrict__ kf_fc1_w, const float* __restrict__ kf_fc1_b,
    const float* __restrict__ kf_fc2_w, const float* __restrict__ kf_fc2_b,
    const float* __restrict__ conv2_w, const float* __restrict__ conv2_b,
    const float* __restrict__ fc1_w, const float* __restrict__ fc1_b,
    const float* __restrict__ fc2_w, const float* __restrict__ fc2_b,
    float* __restrict__ out, int N)
{
    extern __shared__ __align__(16) float s[];

    const int bn  = blockIdx.x;
    const int tid = threadIdx.x;
    const int i0  = 2 * bn;           // first image of this CTA

    // ================= Stage 0: stage inputs into smem =================
    {
        // images (float4)
        #pragma unroll
        for (int img = 0; img < 2; img++) {
            if (i0 + img < N) {
                const float4* x4 = (const float4*)(x + (i0 + img) * 784);
                float4* sx4 = (float4*)(s + SH_IMG0 + img * IMG_STRIDE + PX);
                for (int i = tid; i < 196; i += TPB) sx4[i] = x4[i];
            }
        }
        // conv weights interleaved by channel pair
        for (int i = tid; i < 392; i += TPB) {
            int c = i / 49, q = i - c * 49;
            s[OFF_W1P + (((c >> 1) * 49 + q) << 1) + (c & 1)] = kf_w1[i];
        }
        for (int i = tid; i < 2000; i += TPB) {
            int c = i / 200, r = i - c * 200;
            s[OFF_W2P + (((c >> 1) * 200 + r) << 1) + (c & 1)] = kf_w2[i];
        }
        for (int i = tid; i < 5000; i += TPB) {
            int c = i / 250, r = i - c * 250;
            s[OFF_CWP + (((c >> 1) * 250 + r) << 1) + (c & 1)] = conv2_w[i];
        }
        if (tid < 8)  s[OFF_B1P + tid] = kf_b1[tid];
        if (tid < 10) s[OFF_B2P + tid] = kf_b2[tid];
        if (tid < 20) s[OFF_CBP + tid] = conv2_b[tid];
        // FC transposes (padded -> conflict-free)
        for (int i = tid; i < 2880; i += TPB) {
            int o = i / 90, q = i - o * 90;
            s[OFF_K1T + q * 33 + o] = kf_fc1_w[i];
        }
        for (int i = tid; i < 1280; i += TPB) {
            int o = i >> 5, q = i & 31;
            s[OFF_K2T + q * 41 + o] = kf_fc2_w[i];
        }
        for (int i = tid; i < 500; i += TPB) {
            int o = i / 50, q = i - o * 50;
            s[OFF_F2T + q * 11 + o] = fc2_w[i];
        }
    }
    __syncthreads();

    // ===== Stage 1: conv7x7 (1->8) + pool + relu -> pooled1 [8][11][11] =====
    // unit = (img, channel-pair, pooled pos). 968 units, light footprint.
    for (int u = tid; u < 968; u += TPB) {
        const int img = u / 484;
        const int t   = u - img * 484;
        const int cp  = t / 121;
        const int r2  = t - cp * 121;
        const int pi  = r2 / 11;
        const int pj  = r2 - pi * 11;
        const float* sx = s + SH_IMG0 + img * IMG_STRIDE + PX;
        const u64* wp = (const u64*)(s + OFF_W1P) + cp * 49;
        const u64 bias = ((const u64*)(s + OFF_B1P))[cp];
        u64 a00 = bias, a01 = bias, a10 = bias, a11 = bias;
        #pragma unroll
        for (int r = 0; r < 8; r++) {
            const float* row = sx + (2 * pi + r) * 28 + 2 * pj;
            u64 ap[8];
            #pragma unroll
            for (int j = 0; j < 8; j++) ap[j] = packdup(row[j]);
            if (r < 7) {
                const u64* w = wp + r * 7;
                #pragma unroll
                for (int v = 0; v < 7; v++) {
                    const u64 wv = w[v];
                    a00 = fma2(ap[v],     wv, a00);
                    a01 = fma2(ap[v + 1], wv, a01);
                }
            }
            if (r >= 1) {
                const u64* w = wp + (r - 1) * 7;
                #pragma unroll
                for (int v = 0; v < 7; v++) {
                    const u64 wv = w[v];
                    a10 = fma2(ap[v],     wv, a10);
                    a11 = fma2(ap[v + 1], wv, a11);
                }
            }
        }
        float p0, p1, q0, q1, r0, r1, t0, t1;
        unpk(a00, p0, p1); unpk(a01, q0, q1); unpk(a10, r0, r1); unpk(a11, t0, t1);
        float m0 = fmaxf(fmaxf(p0, q0), fmaxf(r0, t0));
        float m1 = fmaxf(fmaxf(p1, q1), fmaxf(r1, t1));
        float* buf = s + SH_IMG0 + img * IMG_STRIDE + PBUF;
        buf[(2 * cp)     * 121 + pi * 11 + pj] = fmaxf(m0, 0.0f);
        buf[(2 * cp + 1) * 121 + pi * 11 + pj] = fmaxf(m1, 0.0f);
    }
    __syncthreads();

    // ===== Stage 2: conv5x5 (8->10) + pool + relu -> f [10][3][3] =====
    // unit = (img, cp, pos). 90 units.
    if (tid < 90) {
        const int img = tid / 45;
        const int t   = tid - img * 45;
        const int cp  = t / 9;
        const int pos = t - cp * 9;
        const int pi  = pos / 3;
        const int pj  = pos - pi * 3;
        const float* buf = s + SH_IMG0 + img * IMG_STRIDE + PBUF;
        const u64 bias = ((const u64*)(s + OFF_B2P))[cp];
        u64 a00 = bias, a01 = bias, a10 = bias, a11 = bias;
        for (int ci = 0; ci < 8; ci++) {
            const u64* wp = (const u64*)(s + OFF_W2P) + (cp * 8 + ci) * 25;
            #pragma unroll
            for (int r = 0; r < 6; r++) {
                const float* row = buf + ci * 121 + (2 * pi + r) * 11 + 2 * pj;
                u64 ap[6];
                #pragma unroll
                for (int j = 0; j < 6; j++) ap[j] = packdup(row[j]);
                if (r < 5) {
                    const u64* w = wp + r * 5;
                    #pragma unroll
                    for (int v = 0; v < 5; v++) {
                        const u64 wv = w[v];
                        a00 = fma2(ap[v],     wv, a00);
                        a01 = fma2(ap[v + 1], wv, a01);
                    }
                }
                if (r >= 1) {
                    const u64* w = wp + (r - 1) * 5;
                    #pragma unroll
                    for (int v = 0; v < 5; v++) {
                        const u64 wv = w[v];
                        a10 = fma2(ap[v],     wv, a10);
                        a11 = fma2(ap[v + 1], wv, a11);
                    }
                }
            }
        }
        float p0, p1, q0, q1, r0, r1, t0, t1;
        unpk(a00, p0, p1); unpk(a01, q0, q1); unpk(a10, r0, r1); unpk(a11, t0, t1);
        float m0 = fmaxf(fmaxf(p0, q0), fmaxf(r0, t0));
        float m1 = fmaxf(fmaxf(p1, q1), fmaxf(r1, t1));
        float* f = s + SH_IMG0 + img * IMG_STRIDE + PF;
        f[(2 * cp)     * 9 + pos] = fmaxf(m0, 0.0f);
        f[(2 * cp + 1) * 9 + pos] = fmaxf(m1, 0.0f);
    }
    __syncthreads();

    // ===== Stage 3a: hypernet fc1 90->32 relu (64 threads) =====
    if (tid < 64) {
        const int img = tid >> 5;
        const int o   = tid & 31;
        const float* f = s + SH_IMG0 + img * IMG_STRIDE + PF;
        float acc = kf_fc1_b[o];
        #pragma unroll 6
        for (int q = 0; q < 90; q++)
            acc = fmaf(f[q], s[OFF_K1T + q * 33 + o], acc);
        s[SH_IMG0 + img * IMG_STRIDE + PH + o] = fmaxf(acc, 0.0f);
    }
    __syncthreads();
    // ===== Stage 3b: hypernet fc2 32->40 (80 threads) =====
    if (tid < 80) {
        const int img = tid / 40;
        const int o   = tid - img * 40;
        const float* h = s + SH_IMG0 + img * IMG_STRIDE + PH;
        float acc = kf_fc2_b[o];
        #pragma unroll
        for (int q = 0; q < 32; q++)
            acc = fmaf(h[q], s[OFF_K2T + q * 41 + o], acc);
        s[SH_IMG0 + img * IMG_STRIDE + PK + o] = acc;
    }
    __syncthreads();

    // ===== Stage 4: dynamic 2x2 conv + pool + relu -> pooled3 [10][13][13] =====
    for (int it = tid; it < 3380; it += TPB) {
        const int img = it / 1690;
        const int t   = it - img * 1690;
        const int c   = t / 169;
        const int rem = t - c * 169;
        const int pi  = rem / 13;
        const int pj  = rem - pi * 13;
        const float* base = s + SH_IMG0 + img * IMG_STRIDE;
        const float k00 = base[PK + c * 4 + 0];
        const float k01 = base[PK + c * 4 + 1];
        const float k10 = base[PK + c * 4 + 2];
        const float k11 = base[PK + c * 4 + 3];
        float a[3][3];
        #pragma unroll
        for (int u2 = 0; u2 < 3; u2++)
            #pragma unroll
            for (int v = 0; v < 3; v++)
                a[u2][v] = base[PX + (2 * pi + u2) * 28 + 2 * pj + v];
        float m = -INFINITY;
        #pragma unroll
        for (int di = 0; di < 2; di++)
            #pragma unroll
            for (int dj = 0; dj < 2; dj++) {
                float cv = a[di][dj] * k00;
                cv = fmaf(a[di][dj + 1],     k01, cv);
                cv = fmaf(a[di + 1][dj],     k10, cv);
                cv = fmaf(a[di + 1][dj + 1], k11, cv);
                m = fmaxf(m, cv);
            }
        s[SH_IMG0 + img * IMG_STRIDE + PBUF + t] = fmaxf(m, 0.0f);
    }
    __syncthreads();

    // ===== Stage 5: conv5x5 (10->20) + pool + relu -> pooled4 [20][4][4] =====
    // unit = (img, cp, pos). 320 units.
    if (tid < 320) {
        const int img = tid / 160;
        const int t   = tid - img * 160;
        const int cp  = t / 16;
        const int pos = t - cp * 16;
        const int pi  = pos / 4;
        const int pj  = pos - pi * 4;
        const float* buf = s + SH_IMG0 + img * IMG_STRIDE + PBUF;
        const u64 bias = ((const u64*)(s + OFF_CBP))[cp];
        u64 a00 = bias, a01 = bias, a10 = bias, a11 = bias;
        for (int ci = 0; ci < 10; ci++) {
            const u64* wp = (const u64*)(s + OFF_CWP) + (cp * 10 + ci) * 25;
            #pragma unroll
            for (int r = 0; r < 6; r++) {
                const float* row = buf + ci * 169 + (2 * pi + r) * 13 + 2 * pj;
                u64 ap[6];
                #pragma unroll
                for (int j = 0; j < 6; j++) ap[j] = packdup(row[j]);
                if (r < 5) {
                    const u64* w = wp + r * 5;
                    #pragma unroll
                    for (int v = 0; v < 5; v++) {
                        const u64 wv = w[v];
                        a00 = fma2(ap[v],     wv, a00);
                        a01 = fma2(ap[v + 1], wv, a01);
                    }
                }
                if (r >= 1) {
                    const u64* w = wp + (r - 1) * 5;
                    #pragma unroll
                    for (int v = 0; v < 5; v++) {
                        const u64 wv = w[v];
                        a10 = fma2(ap[v],     wv, a10);
                        a11 = fma2(ap[v + 1], wv, a11);
                    }
                }
            }
        }
        float p0, p1, q0, q1, r0, r1, t0, t1;
        unpk(a00, p0, p1); unpk(a01, q0, q1); unpk(a10, r0, r1); unpk(a11, t0, t1);
        float m0 = fmaxf(fmaxf(p0, q0), fmaxf(r0, t0));
        float m1 = fmaxf(fmaxf(p1, q1), fmaxf(r1, t1));
        float* p4 = s + SH_IMG0 + img * IMG_STRIDE + PP4;
        p4[(2 * cp)     * 16 + pos] = fmaxf(m0, 0.0f);
        p4[(2 * cp + 1) * 16 + pos] = fmaxf(m1, 0.0f);
    }
    __syncthreads();

    // ===== Stage 6: fc1 320->50 relu, warp per (img,o) =====
    {
        const int warp = tid >> 5;
        const int lane = tid & 31;
        for (int u = warp; u < 100; u += (TPB / 32)) {
            const int img = u / 50;
            const int o   = u - img * 50;
            const float4* wr = (const float4*)(fc1_w + o * 320);
            const float4* pr = (const float4*)(s + SH_IMG0 + img * IMG_STRIDE + PP4);
            float acc = 0.0f;
            #pragma unroll
            for (int k = 0; k < 3; k++) {
                const int i = lane + 32 * k;
                if (i < 80) {
                    float4 w4 = wr[i];
                    float4 p4 = pr[i];
                    acc = fmaf(w4.x, p4.x, fmaf(w4.y, p4.y,
                          fmaf(w4.z, p4.z, fmaf(w4.w, p4.w, acc))));
                }
            }
            #pragma unroll
            for (int off = 16; off > 0; off >>= 1)
                acc += __shfl_xor_sync(0xffffffffu, acc, off);
            if (lane == 0)
                s[SH_IMG0 + img * IMG_STRIDE + PY1 + o] = fmaxf(acc + fc1_b[o], 0.0f);
        }
    }
    __syncthreads();

    // ===== Stage 7: fc2 50->10 + log_softmax =====
    if (tid < 20) {
        const int img = tid / 10;
        const int o   = tid - img * 10;
        const float* y1 = s + SH_IMG0 + img * IMG_STRIDE + PY1;
        float acc = fc2_b[o];
        #pragma unroll 10
        for (int q = 0; q < 50; q++)
            acc = fmaf(y1[q], s[OFF_F2T + q * 11 + o], acc);
        s[SH_IMG0 + img * IMG_STRIDE + PLG + o] = acc;
    }
    __syncthreads();
    if (tid < 2) {
        const float* lg = s + SH_IMG0 + tid * IMG_STRIDE + PLG;
        float mx = lg[0];
        #pragma unroll
        for (int q = 1; q < 10; q++) mx = fmaxf(mx, lg[q]);
        float sum = 0.0f;
        #pragma unroll
        for (int q = 0; q < 10; q++) sum += expf(lg[q] - mx);
        s[SH_IMG0 + tid * IMG_STRIDE + PLG + 12] = mx + logf(sum);
    }
    __syncthreads();
    if (tid < 20) {
        const int img = tid / 10;
        const int o   = tid - img * 10;
        if (i0 + img < N) {
            const float* lg = s + SH_IMG0 + img * IMG_STRIDE + PLG;
            out[(i0 + img) * 10 + o] = lg[o] - lg[12];
        }
    }
}

extern "C" void kernel_launch(void* const* d_in, const int* in_sizes, int n_in,
                              void* d_out, int out_size) {
    const float* x        = (const float*)d_in[0];
    const float* kf_w1    = (const float*)d_in[1];
    const float* kf_b1    = (const float*)d_in[2];
    const float* kf_w2    = (const float*)d_in[3];
    const float* kf_b2    = (const float*)d_in[4];
    const float* kf_fc1_w = (const float*)d_in[5];
    const float* kf_fc1_b = (const float*)d_in[6];
    const float* kf_fc2_w = (const float*)d_in[7];
    const float* kf_fc2_b = (const float*)d_in[8];
    const float* conv2_w  = (const float*)d_in[9];
    const float* conv2_b  = (const float*)d_in[10];
    const float* fc1_w    = (const float*)d_in[11];
    const float* fc1_b    = (const float*)d_in[12];
    const float* fc2_w    = (const float*)d_in[13];
    const float* fc2_b    = (const float*)d_in[14];
    float* out = (float*)d_out;

    const int N = in_sizes[0] / 784;
    const int grid = (N + 1) / 2;
    cudaFuncSetAttribute(fused_net_kernel,
                         cudaFuncAttributeMaxDynamicSharedMemorySize, SMEM_BYTES);
    fused_net_kernel<<<grid, TPB, SMEM_BYTES>>>(x, kf_w1, kf_b1, kf_w2, kf_b2,
                                                kf_fc1_w, kf_fc1_b, kf_fc2_w, kf_fc2_b,
                                                conv2_w, conv2_b, fc1_w, fc1_b,
                                                fc2_w, fc2_b, out, N);
}

// round 4
// speedup vs baseline: 1.6394x; 1.0081x over previous
#include <cuda_runtime.h>
#include <math.h>

#define TPB 352
typedef unsigned long long u64;

// ---- packed fp32x2 helpers (sm_103a) ----
__device__ __forceinline__ u64 packdup(float a) {
    u64 r; asm("mov.b64 %0,{%1,%1};" : "=l"(r) : "f"(a)); return r;
}
__device__ __forceinline__ u64 fma2(u64 a, u64 b, u64 c) {
    u64 d; asm("fma.rn.f32x2 %0,%1,%2,%3;" : "=l"(d) : "l"(a), "l"(b), "l"(c)); return d;
}
__device__ __forceinline__ void unpk(u64 x, float& lo, float& hi) {
    asm("mov.b64 {%0,%1},%2;" : "=f"(lo), "=f"(hi) : "l"(x));
}

// ---- shared memory layout (floats) ----
#define OFF_W1P 0        // [4 pair][49] x2       (392)
#define OFF_W2P 392      // [5 pair][8ci][25] x2  (2000)
#define OFF_CWP 2392     // [10 pair][10ci][25]x2 (5000)
#define OFF_B1P 7392     // (8)
#define OFF_B2P 7400     // (10)
#define OFF_CBP 7410     // (20) -> 7430 pad 7432
#define OFF_K1T 7432     // kf_fc1_w^T [90][33]   (2970)
#define OFF_K2T 10402    // kf_fc2_w^T [32][41]   (1312)
#define OFF_F2T 11714    // fc2_w^T    [50][11]   (550) -> 12264 pad 12272
// per-image blocks (x2)
#define SH_IMG0 12272
#define IMG_STRIDE 3176       // x4B = 12704: not a multiple of 128 (bank shift), 16B aligned
#define PX   0                // [28][28] (784)
#define PBUF 784              // pooled1 [8][11][12]=1056 / pooled3 [10][13][14]=1820
#define PF   2604             // (90)
#define PH   2694             // (32)
#define PK   2726             // (40) -> 2766 pad 2768
#define PP4  2768             // [20][4][4] (320), 16B aligned
#define PY1  3088             // (64)
#define PLG  3152             // (16) -> 3168
#define SMEM_FLOATS (SH_IMG0 + 2 * IMG_STRIDE)
#define SMEM_BYTES  (SMEM_FLOATS * 4)

__global__ __launch_bounds__(TPB, 3) void fused_net_kernel(
    const float* __restrict__ x,
    const float* __restrict__ kf_w1, const float* __restrict__ kf_b1,
    const float* __restrict__ kf_w2, const float* __restrict__ kf_b2,
    const float* __restrict__ kf_fc1_w, const float* __restrict__ kf_fc1_b,
    const float* __restrict__ kf_fc2_w, const float* __restrict__ kf_fc2_b,
    const float* __restrict__ conv2_w, const float* __restrict__ conv2_b,
    const float* __restrict__ fc1_w, const float* __restrict__ fc1_b,
    const float* __restrict__ fc2_w, const float* __restrict__ fc2_b,
    float* __restrict__ out, int N)
{
    extern __shared__ __align__(16) float s[];

    const int bn  = blockIdx.x;
    const int tid = threadIdx.x;
    const int i0  = 2 * bn;

    // ================= Stage 0: stage inputs into smem =================
    {
        #pragma unroll
        for (int img = 0; img < 2; img++) {
            if (i0 + img < N) {
                const float4* x4 = (const float4*)(x + (i0 + img) * 784);
                float4* sx4 = (float4*)(s + SH_IMG0 + img * IMG_STRIDE + PX);
                for (int i = tid; i < 196; i += TPB) sx4[i] = x4[i];
            }
        }
        for (int i = tid; i < 392; i += TPB) {
            int c = i / 49, q = i - c * 49;
            s[OFF_W1P + (((c >> 1) * 49 + q) << 1) + (c & 1)] = kf_w1[i];
        }
        for (int i = tid; i < 2000; i += TPB) {
            int c = i / 200, r = i - c * 200;
            s[OFF_W2P + (((c >> 1) * 200 + r) << 1) + (c & 1)] = kf_w2[i];
        }
        for (int i = tid; i < 5000; i += TPB) {
            int c = i / 250, r = i - c * 250;
            s[OFF_CWP + (((c >> 1) * 250 + r) << 1) + (c & 1)] = conv2_w[i];
        }
        if (tid < 8)  s[OFF_B1P + tid] = kf_b1[tid];
        if (tid < 10) s[OFF_B2P + tid] = kf_b2[tid];
        if (tid < 20) s[OFF_CBP + tid] = conv2_b[tid];
        for (int i = tid; i < 2880; i += TPB) {
            int o = i / 90, q = i - o * 90;
            s[OFF_K1T + q * 33 + o] = kf_fc1_w[i];
        }
        for (int i = tid; i < 1280; i += TPB) {
            int o = i >> 5, q = i & 31;
            s[OFF_K2T + q * 41 + o] = kf_fc2_w[i];
        }
        for (int i = tid; i < 500; i += TPB) {
            int o = i / 50, q = i - o * 50;
            s[OFF_F2T + q * 11 + o] = fc2_w[i];
        }
    }
    __syncthreads();

    // ===== Stage 1: conv7x7 (1->8) + pool + relu -> pooled1 [8][11][12pad] =====
    // unit = (img, quad of 4 out channels, pooled pos). 484 units.
    for (int u = tid; u < 484; u += TPB) {
        const int img = u / 242;
        const int t   = u - img * 242;
        const int qd  = t / 121;
        const int pos = t - qd * 121;
        const int pi  = pos / 11;
        const int pj  = pos - pi * 11;
        const float* sx = s + SH_IMG0 + img * IMG_STRIDE + PX;
        const u64* wp0 = (const u64*)(s + OFF_W1P) + (2 * qd) * 49;
        const u64* wp1 = wp0 + 49;
        const u64 b0 = ((const u64*)(s + OFF_B1P))[2 * qd];
        const u64 b1 = ((const u64*)(s + OFF_B1P))[2 * qd + 1];
        u64 A0[4] = {b0, b0, b0, b0};   // pair 0: 4 conv window positions
        u64 A1[4] = {b1, b1, b1, b1};   // pair 1
        #pragma unroll
        for (int r = 0; r < 8; r++) {
            const float2* row = (const float2*)(sx + (2 * pi + r) * 28 + 2 * pj);
            u64 pd[8];
            #pragma unroll
            for (int j = 0; j < 4; j++) {
                float2 f = row[j];
                pd[2 * j]     = packdup(f.x);
                pd[2 * j + 1] = packdup(f.y);
            }
            if (r < 7) {
                #pragma unroll
                for (int v = 0; v < 7; v++) {
                    const u64 w0 = wp0[r * 7 + v], w1 = wp1[r * 7 + v];
                    A0[0] = fma2(pd[v],     w0, A0[0]);
                    A0[1] = fma2(pd[v + 1], w0, A0[1]);
                    A1[0] = fma2(pd[v],     w1, A1[0]);
                    A1[1] = fma2(pd[v + 1], w1, A1[1]);
                }
            }
            if (r >= 1) {
                #pragma unroll
                for (int v = 0; v < 7; v++) {
                    const u64 w0 = wp0[(r - 1) * 7 + v], w1 = wp1[(r - 1) * 7 + v];
                    A0[2] = fma2(pd[v],     w0, A0[2]);
                    A0[3] = fma2(pd[v + 1], w0, A0[3]);
                    A1[2] = fma2(pd[v],     w1, A1[2]);
                    A1[3] = fma2(pd[v + 1], w1, A1[3]);
                }
            }
        }
        float* buf = s + SH_IMG0 + img * IMG_STRIDE + PBUF;
        {
            float p0, p1, q0, q1, r0, r1, t0, t1;
            unpk(A0[0], p0, p1); unpk(A0[1], q0, q1); unpk(A0[2], r0, r1); unpk(A0[3], t0, t1);
            buf[(4 * qd)     * 132 + pi * 12 + pj] = fmaxf(fmaxf(fmaxf(p0, q0), fmaxf(r0, t0)), 0.0f);
            buf[(4 * qd + 1) * 132 + pi * 12 + pj] = fmaxf(fmaxf(fmaxf(p1, q1), fmaxf(r1, t1)), 0.0f);
            unpk(A1[0], p0, p1); unpk(A1[1], q0, q1); unpk(A1[2], r0, r1); unpk(A1[3], t0, t1);
            buf[(4 * qd + 2) * 132 + pi * 12 + pj] = fmaxf(fmaxf(fmaxf(p0, q0), fmaxf(r0, t0)), 0.0f);
            buf[(4 * qd + 3) * 132 + pi * 12 + pj] = fmaxf(fmaxf(fmaxf(p1, q1), fmaxf(r1, t1)), 0.0f);
        }
    }
    __syncthreads();

    // ===== Stage 2: conv5x5 (8->10) + pool + relu -> f [10][3][3] =====
    // unit = (img, cp, pos), split over ci halves; pair combine via shfl. 180(+12 dummy) threads.
    if (tid < 192) {
        const int uu   = tid >> 1;
        const int half = tid & 1;
        const bool valid = uu < 90;
        const int u   = valid ? uu : 0;
        const int img = u / 45;
        const int t   = u - img * 45;
        const int cp  = t / 9;
        const int pos = t - cp * 9;
        const int pi  = pos / 3;
        const int pj  = pos - pi * 3;
        const float* buf = s + SH_IMG0 + img * IMG_STRIDE + PBUF;
        const u64 bias = ((const u64*)(s + OFF_B2P))[cp];
        const u64 zero = 0ull;
        u64 A[4];
        #pragma unroll
        for (int k = 0; k < 4; k++) A[k] = half ? zero : bias;
        #pragma unroll
        for (int cc = 0; cc < 4; cc++) {
            const int ci = 4 * half + cc;
            const u64* wp = (const u64*)(s + OFF_W2P) + (cp * 8 + ci) * 25;
            #pragma unroll
            for (int r = 0; r < 6; r++) {
                const float2* row = (const float2*)(buf + ci * 132 + (2 * pi + r) * 12 + 2 * pj);
                u64 pd[6];
                #pragma unroll
                for (int j = 0; j < 3; j++) {
                    float2 f = row[j];
                    pd[2 * j]     = packdup(f.x);
                    pd[2 * j + 1] = packdup(f.y);
                }
                if (r < 5) {
                    #pragma unroll
                    for (int v = 0; v < 5; v++) {
                        const u64 wv = wp[r * 5 + v];
                        A[0] = fma2(pd[v],     wv, A[0]);
                        A[1] = fma2(pd[v + 1], wv, A[1]);
                    }
                }
                if (r >= 1) {
                    #pragma unroll
                    for (int v = 0; v < 5; v++) {
                        const u64 wv = wp[(r - 1) * 5 + v];
                        A[2] = fma2(pd[v],     wv, A[2]);
                        A[3] = fma2(pd[v + 1], wv, A[3]);
                    }
                }
            }
        }
        // combine halves and reduce
        float me = -INFINITY, mo = -INFINITY;
        #pragma unroll
        for (int k = 0; k < 4; k++) {
            float lo, hi;
            unpk(A[k], lo, hi);
            lo += __shfl_xor_sync(0xffffffffu, lo, 1);
            hi += __shfl_xor_sync(0xffffffffu, hi, 1);
            me = fmaxf(me, lo);
            mo = fmaxf(mo, hi);
        }
        if (valid) {
            float* f = s + SH_IMG0 + img * IMG_STRIDE + PF;
            if (half == 0) f[(2 * cp)     * 9 + pos] = fmaxf(me, 0.0f);
            else           f[(2 * cp + 1) * 9 + pos] = fmaxf(mo, 0.0f);
        }
    }
    __syncthreads();

    // ===== Stage 3a: hypernet fc1 90->32 relu =====
    if (tid < 64) {
        const int img = tid >> 5;
        const int o   = tid & 31;
        const float* f = s + SH_IMG0 + img * IMG_STRIDE + PF;
        float acc = kf_fc1_b[o];
        #pragma unroll 6
        for (int q = 0; q < 90; q++)
            acc = fmaf(f[q], s[OFF_K1T + q * 33 + o], acc);
        s[SH_IMG0 + img * IMG_STRIDE + PH + o] = fmaxf(acc, 0.0f);
    }
    __syncthreads();
    // ===== Stage 3b: hypernet fc2 32->40 =====
    if (tid < 80) {
        const int img = tid / 40;
        const int o   = tid - img * 40;
        const float* h = s + SH_IMG0 + img * IMG_STRIDE + PH;
        float acc = kf_fc2_b[o];
        #pragma unroll
        for (int q = 0; q < 32; q++)
            acc = fmaf(h[q], s[OFF_K2T + q * 41 + o], acc);
        s[SH_IMG0 + img * IMG_STRIDE + PK + o] = acc;
    }
    __syncthreads();

    // ===== Stage 4: dynamic 2x2 conv + pool + relu -> pooled3 [10][13][14pad] =====
    for (int it = tid; it < 3380; it += TPB) {
        const int img = it / 1690;
        const int t   = it - img * 1690;
        const int c   = t / 169;
        const int rem = t - c * 169;
        const int pi  = rem / 13;
        const int pj  = rem - pi * 13;
        const float* base = s + SH_IMG0 + img * IMG_STRIDE;
        const float k00 = base[PK + c * 4 + 0];
        const float k01 = base[PK + c * 4 + 1];
        const float k10 = base[PK + c * 4 + 2];
        const float k11 = base[PK + c * 4 + 3];
        float a[3][3];
        #pragma unroll
        for (int u2 = 0; u2 < 3; u2++) {
            const float2 f01 = *(const float2*)(base + PX + (2 * pi + u2) * 28 + 2 * pj);
            a[u2][0] = f01.x; a[u2][1] = f01.y;
            a[u2][2] = base[PX + (2 * pi + u2) * 28 + 2 * pj + 2];
        }
        float m = -INFINITY;
        #pragma unroll
        for (int di = 0; di < 2; di++)
            #pragma unroll
            for (int dj = 0; dj < 2; dj++) {
                float cv = a[di][dj] * k00;
                cv = fmaf(a[di][dj + 1],     k01, cv);
                cv = fmaf(a[di + 1][dj],     k10, cv);
                cv = fmaf(a[di + 1][dj + 1], k11, cv);
                m = fmaxf(m, cv);
            }
        s[SH_IMG0 + img * IMG_STRIDE + PBUF + c * 182 + pi * 14 + pj] = fmaxf(m, 0.0f);
    }
    __syncthreads();

    // ===== Stage 5: conv5x5 (10->20) + pool + relu -> pooled4 [20][4][4] =====
    // unit = (img, cp, pos). 320 units.
    if (tid < 320) {
        const int img = tid / 160;
        const int t   = tid - img * 160;
        const int cp  = t / 16;
        const int pos = t - cp * 16;
        const int pi  = pos / 4;
        const int pj  = pos - pi * 4;
        const float* buf = s + SH_IMG0 + img * IMG_STRIDE + PBUF;
        const u64 bias = ((const u64*)(s + OFF_CBP))[cp];
        u64 A[4] = {bias, bias, bias, bias};
        #pragma unroll 2
        for (int ci = 0; ci < 10; ci++) {
            const u64* wp = (const u64*)(s + OFF_CWP) + (cp * 10 + ci) * 25;
            #pragma unroll
            for (int r = 0; r < 6; r++) {
                const float2* row = (const float2*)(buf + ci * 182 + (2 * pi + r) * 14 + 2 * pj);
                u64 pd[6];
                #pragma unroll
                for (int j = 0; j < 3; j++) {
                    float2 f = row[j];
                    pd[2 * j]     = packdup(f.x);
                    pd[2 * j + 1] = packdup(f.y);
                }
                if (r < 5) {
                    #pragma unroll
                    for (int v = 0; v < 5; v++) {
                        const u64 wv = wp[r * 5 + v];
                        A[0] = fma2(pd[v],     wv, A[0]);
                        A[1] = fma2(pd[v + 1], wv, A[1]);
                    }
                }
                if (r >= 1) {
                    #pragma unroll
                    for (int v = 0; v < 5; v++) {
                        const u64 wv = wp[(r - 1) * 5 + v];
                        A[2] = fma2(pd[v],     wv, A[2]);
                        A[3] = fma2(pd[v + 1], wv, A[3]);
                    }
                }
            }
        }
        float p0, p1, q0, q1, r0, r1, t0, t1;
        unpk(A[0], p0, p1); unpk(A[1], q0, q1); unpk(A[2], r0, r1); unpk(A[3], t0, t1);
        float m0 = fmaxf(fmaxf(p0, q0), fmaxf(r0, t0));
        float m1 = fmaxf(fmaxf(p1, q1), fmaxf(r1, t1));
        float* p4 = s + SH_IMG0 + img * IMG_STRIDE + PP4;
        p4[(2 * cp)     * 16 + pos] = fmaxf(m0, 0.0f);
        p4[(2 * cp + 1) * 16 + pos] = fmaxf(m1, 0.0f);
    }
    __syncthreads();

    // ===== Stage 6: fc1 320->50 relu, warp per (img,o) =====
    {
        const int warp = tid >> 5;
        const int lane = tid & 31;
        for (int u = warp; u < 100; u += (TPB / 32)) {
            const int img = u / 50;
            const int o   = u - img * 50;
            const float4* wr = (const float4*)(fc1_w + o * 320);
            const float4* pr = (const float4*)(s + SH_IMG0 + img * IMG_STRIDE + PP4);
            float acc = 0.0f;
            #pragma unroll
            for (int k = 0; k < 3; k++) {
                const int i = lane + 32 * k;
                if (i < 80) {
                    float4 w4 = wr[i];
                    float4 p4 = pr[i];
                    acc = fmaf(w4.x, p4.x, fmaf(w4.y, p4.y,
                          fmaf(w4.z, p4.z, fmaf(w4.w, p4.w, acc))));
                }
            }
            #pragma unroll
            for (int off = 16; off > 0; off >>= 1)
                acc += __shfl_xor_sync(0xffffffffu, acc, off);
            if (lane == 0)
                s[SH_IMG0 + img * IMG_STRIDE + PY1 + o] = fmaxf(acc + fc1_b[o], 0.0f);
        }
    }
    __syncthreads();

    // ===== Stage 7: fc2 50->10 + log_softmax =====
    if (tid < 20) {
        const int img = tid / 10;
        const int o   = tid - img * 10;
        const float* y1 = s + SH_IMG0 + img * IMG_STRIDE + PY1;
        float acc = fc2_b[o];
        #pragma unroll 10
        for (int q = 0; q < 50; q++)
            acc = fmaf(y1[q], s[OFF_F2T + q * 11 + o], acc);
        s[SH_IMG0 + img * IMG_STRIDE + PLG + o] = acc;
    }
    __syncthreads();
    if (tid < 2) {
        const float* lg = s + SH_IMG0 + tid * IMG_STRIDE + PLG;
        float mx = lg[0];
        #pragma unroll
        for (int q = 1; q < 10; q++) mx = fmaxf(mx, lg[q]);
        float sum = 0.0f;
        #pragma unroll
        for (int q = 0; q < 10; q++) sum += expf(lg[q] - mx);
        s[SH_IMG0 + tid * IMG_STRIDE + PLG + 12] = mx + logf(sum);
    }
    __syncthreads();
    if (tid < 20) {
        const int img = tid / 10;
        const int o   = tid - img * 10;
        if (i0 + img < N) {
            const float* lg = s + SH_IMG0 + img * IMG_STRIDE + PLG;
            out[(i0 + img) * 10 + o] = lg[o] - lg[12];
        }
    }
}

extern "C" void kernel_launch(void* const* d_in, const int* in_sizes, int n_in,
                              void* d_out, int out_size) {
    const float* x        = (const float*)d_in[0];
    const float* kf_w1    = (const float*)d_in[1];
    const float* kf_b1    = (const float*)d_in[2];
    const float* kf_w2    = (const float*)d_in[3];
    const float* kf_b2    = (const float*)d_in[4];
    const float* kf_fc1_w = (const float*)d_in[5];
    const float* kf_fc1_b = (const float*)d_in[6];
    const float* kf_fc2_w = (const float*)d_in[7];
    const float* kf_fc2_b = (const float*)d_in[8];
    const float* conv2_w  = (const float*)d_in[9];
    const float* conv2_b  = (const float*)d_in[10];
    const float* fc1_w    = (const float*)d_in[11];
    const float* fc1_b    = (const float*)d_in[12];
    const float* fc2_w    = (const float*)d_in[13];
    const float* fc2_b    = (const float*)d_in[14];
    float* out = (float*)d_out;

    const int N = in_sizes[0] / 784;
    const int grid = (N + 1) / 2;
    cudaFuncSetAttribute(fused_net_kernel,
                         cudaFuncAttributeMaxDynamicSharedMemorySize, SMEM_BYTES);
    fused_net_kernel<<<grid, TPB, SMEM_BYTES>>>(x, kf_w1, kf_b1, kf_w2, kf_b2,
                                                kf_fc1_w, kf_fc1_b, kf_fc2_w, kf_fc2_b,
                                                conv2_w, conv2_b, fc1_w, fc1_b,
                                                fc2_w, fc2_b, out, N);
}